// round 16
// baseline (speedup 1.0000x reference)
#include <cuda_runtime.h>
#include <cuda_fp16.h>
#include <math.h>
#include <stdint.h>

#define N_TOK   4096
#define D_MODEL 512
#define D3      1536
#define MLP_DIM 2048
#define HEADS   8
#define DHEAD   64
#define GRID_SZ 80

// ---------------- scratch (no allocations allowed) ----------------
__device__ float g_h  [N_TOK * D_MODEL];   // used as __half
__device__ float g_qkv[N_TOK * D3];        // used as __half
__device__ float g_ao [N_TOK * D_MODEL];   // used as __half
__device__ float g_xa [N_TOK * D_MODEL];
__device__ float g_x1 [N_TOK * D_MODEL];
__device__ float g_x2 [N_TOK * D_MODEL];
__device__ float g_mlp[N_TOK * MLP_DIM];   // used as __half
__device__ int   g_cellmap[GRID_SZ * GRID_SZ];
__device__ int   g_pmin[2];

// fp16 pre-converted weights (element counts)
#define WQKV_SZ (2 * D_MODEL * D3)
#define WO_SZ   (2 * D_MODEL * D_MODEL)
#define W1_SZ   (2 * D_MODEL * MLP_DIM)
#define W2_SZ   (2 * MLP_DIM * D_MODEL)
#define WTOT_SZ (WQKV_SZ + WO_SZ + W1_SZ + W2_SZ)
__device__ float g_wc[WTOT_SZ / 2];  // as __half

// ---------------- helpers ----------------
__device__ __forceinline__ uint32_t h2_as_u32(__half2 h) {
    return *(uint32_t*)&h;
}

__device__ __forceinline__ float warp_sum(float v) {
#pragma unroll
    for (int o = 16; o > 0; o >>= 1) v += __shfl_xor_sync(0xffffffffu, v, o);
    return v;
}

// fp16 mma m16n8k16, fp32 accum
__device__ __forceinline__ void mma16h(float* d, const uint32_t* a,
                                       uint32_t b0, uint32_t b1) {
    asm volatile(
        "mma.sync.aligned.m16n8k16.row.col.f32.f16.f16.f32 "
        "{%0,%1,%2,%3},{%4,%5,%6,%7},{%8,%9},{%0,%1,%2,%3};"
        : "+f"(d[0]), "+f"(d[1]), "+f"(d[2]), "+f"(d[3])
        : "r"(a[0]), "r"(a[1]), "r"(a[2]), "r"(a[3]), "r"(b0), "r"(b1));
}

__device__ __forceinline__ void ldsm4(uint32_t* r, const void* p) {
    uint32_t a = (uint32_t)__cvta_generic_to_shared(p);
    asm volatile("ldmatrix.sync.aligned.m8n8.x4.shared.b16 {%0,%1,%2,%3}, [%4];"
        : "=r"(r[0]), "=r"(r[1]), "=r"(r[2]), "=r"(r[3]) : "r"(a));
}
__device__ __forceinline__ void ldsm4t(uint32_t* r, const void* p) {
    uint32_t a = (uint32_t)__cvta_generic_to_shared(p);
    asm volatile("ldmatrix.sync.aligned.m8n8.x4.trans.shared.b16 {%0,%1,%2,%3}, [%4];"
        : "=r"(r[0]), "=r"(r[1]), "=r"(r[2]), "=r"(r[3]) : "r"(a));
}

__device__ __forceinline__ void cp16(void* smem, const void* g) {
    uint32_t s = (uint32_t)__cvta_generic_to_shared(smem);
    asm volatile("cp.async.cg.shared.global [%0], [%1], 16;\n" :: "r"(s), "l"(g));
}
__device__ __forceinline__ void cp_commit() { asm volatile("cp.async.commit_group;\n"); }
template <int NcpW> __device__ __forceinline__ void cp_wait() {
    asm volatile("cp.async.wait_group %0;\n" :: "n"(NcpW));
}

// fast 2^x (FFMA-only); deg-3 poly, err ~1e-4 rel (under fp16 target rounding)
__device__ __forceinline__ float fexp2(float x) {
    float z = x + 12582912.0f;                       // round-to-nearest int
    int   n23 = (__float_as_int(z) - 0x4B400000) << 23;
    float f = x - (z - 12582912.0f);                 // f in [-0.5, 0.5]
    float p = 0.0573608f;
    p = fmaf(p, f, 0.2401269f);
    p = fmaf(p, f, 0.6931674f);
    p = fmaf(p, f, 1.0f);
    return __int_as_float(__float_as_int(p) + n23);  // exponent add (ALU pipe)
}

// ---------------- merged weight fp16 pre-conversion ----------------
__global__ __launch_bounds__(256) void k_cvt4(
    const float* __restrict__ s0, const float* __restrict__ s1,
    const float* __restrict__ s2, const float* __restrict__ s3,
    __half* __restrict__ dst)
{
    int i = (blockIdx.x * 256 + threadIdx.x) << 2;
    if (i >= WTOT_SZ) return;
    const float* src; int off;
    if (i < WQKV_SZ)                         { src = s0; off = 0; }
    else if (i < WQKV_SZ + WO_SZ)            { src = s1; off = WQKV_SZ; }
    else if (i < WQKV_SZ + WO_SZ + W1_SZ)    { src = s2; off = WQKV_SZ + WO_SZ; }
    else                                     { src = s3; off = WQKV_SZ + WO_SZ + W1_SZ; }
    float4 v = *(const float4*)(src + (i - off));
    uint2 o;
    o.x = h2_as_u32(__floats2half2_rn(v.x, v.y));
    o.y = h2_as_u32(__floats2half2_rn(v.z, v.w));
    *(uint2*)(dst + i) = o;
}

// ---------------- LayerNorm ----------------
template <int OUTH>
__global__ __launch_bounds__(128) void k_layernorm(
    const float* __restrict__ x, const float* __restrict__ g,
    const float* __restrict__ b, void* __restrict__ outv)
{
    int row = blockIdx.x;
    const float4* xr = (const float4*)(x + (size_t)row * D_MODEL);
    float4 v = xr[threadIdx.x];
    float s  = v.x + v.y + v.z + v.w;
    float sq = v.x * v.x + v.y * v.y + v.z * v.z + v.w * v.w;

    __shared__ float sh1[4], sh2[4];
    int w = threadIdx.x >> 5, lane = threadIdx.x & 31;
    s = warp_sum(s); sq = warp_sum(sq);
    if (lane == 0) { sh1[w] = s; sh2[w] = sq; }
    __syncthreads();
    float ts = sh1[0] + sh1[1] + sh1[2] + sh1[3];
    float tq = sh2[0] + sh2[1] + sh2[2] + sh2[3];
    float mean = ts * (1.0f / D_MODEL);
    float var  = tq * (1.0f / D_MODEL) - mean * mean;
    float r    = rsqrtf(var + 1e-5f);

    float4 gv = ((const float4*)g)[threadIdx.x];
    float4 bv = ((const float4*)b)[threadIdx.x];
    float4 o;
    o.x = (v.x - mean) * r * gv.x + bv.x;
    o.y = (v.y - mean) * r * gv.y + bv.y;
    o.z = (v.z - mean) * r * gv.z + bv.z;
    o.w = (v.w - mean) * r * gv.w + bv.w;
    if (OUTH) {
        uint2 hh;
        hh.x = h2_as_u32(__floats2half2_rn(o.x, o.y));
        hh.y = h2_as_u32(__floats2half2_rn(o.z, o.w));
        *(uint2*)((__half*)outv + (size_t)row * D_MODEL + threadIdx.x * 4) = hh;
    } else {
        ((float4*)((float*)outv + (size_t)row * D_MODEL))[threadIdx.x] = o;
    }
}

// ---------------- GELU (tanh approx) ----------------
__device__ __forceinline__ float gelu1(float u) {
    return 0.5f * u * (1.0f + tanhf(0.7978845608028654f *
                                    (u + 0.044715f * u * u * u)));
}

// ---------------- FP16 GEMM 128x128, k-tile 32, 3-stage, single-sync ---------
// EPI: 1 bias+gelu -> fp16; 3 bias + (0.125*log2e) Q-scale -> fp16
#define ASTR 40
#define BSTR 136
#define GAS_H (128 * ASTR)   // halves per A stage
#define GBS_H (32 * BSTR)    // halves per B stage
#define GEMM_SMEM ((3 * GAS_H + 3 * GBS_H) * 2)

template <int EPI>
__global__ __launch_bounds__(256, 2) void k_gemm(
    int M, int N, int K,
    const __half* __restrict__ A, const __half* __restrict__ B,
    const float* __restrict__ bias, __half* __restrict__ C)
{
    extern __shared__ __half gsmh[];
    __half* AsBase = gsmh;
    __half* BsBase = gsmh + 3 * GAS_H;

    const int tid  = threadIdx.x;
    const int wid  = tid >> 5, lane = tid & 31;
    const int wr   = wid >> 2, wc   = wid & 3;       // 2x4 warps: 64x32 each
    const int lr   = lane >> 2, lc  = lane & 3;
    const int bx   = blockIdx.x, by = blockIdx.y;

    const int mrow = ((lane >> 3) & 1) * 8 + (lane & 7);
    const int mseg = (lane >> 4) * 8;

    const int am = tid >> 1, ac = (tid & 1) * 16;    // A: row, 2 segs
    const int bk = tid >> 3, bc = (tid & 7) * 16;    // B: row, 2 segs

    const __half* Ab = A + (size_t)(by * 128) * K;
    const __half* Bb = B + bx * 128;

    float acc[4][4][4];
#pragma unroll
    for (int i = 0; i < 4; i++)
#pragma unroll
        for (int j = 0; j < 4; j++)
#pragma unroll
            for (int q = 0; q < 4; q++) acc[i][j][q] = 0.f;

    const int nk = K >> 5;

#pragma unroll
    for (int p = 0; p < 2; ++p) {
        const int k0 = p << 5;
        __half* As = AsBase + p * GAS_H;
        __half* Bs = BsBase + p * GBS_H;
        cp16(&As[am * ASTR + ac],     Ab + (size_t)am * K + k0 + ac);
        cp16(&As[am * ASTR + ac + 8], Ab + (size_t)am * K + k0 + ac + 8);
        cp16(&Bs[bk * BSTR + bc],     Bb + (size_t)(k0 + bk) * N + bc);
        cp16(&Bs[bk * BSTR + bc + 8], Bb + (size_t)(k0 + bk) * N + bc + 8);
        cp_commit();
    }

    int st = 0, wst = 2;
    for (int kt = 0; kt < nk; ++kt) {
        if (kt + 1 < nk) cp_wait<1>(); else cp_wait<0>();
        __syncthreads();
        if (kt + 2 < nk) {
            const int k0 = (kt + 2) << 5;
            __half* As = AsBase + wst * GAS_H;
            __half* Bs = BsBase + wst * GBS_H;
            cp16(&As[am * ASTR + ac],     Ab + (size_t)am * K + k0 + ac);
            cp16(&As[am * ASTR + ac + 8], Ab + (size_t)am * K + k0 + ac + 8);
            cp16(&Bs[bk * BSTR + bc],     Bb + (size_t)(k0 + bk) * N + bc);
            cp16(&Bs[bk * BSTR + bc + 8], Bb + (size_t)(k0 + bk) * N + bc + 8);
            cp_commit();
        }

        const __half* As = AsBase + st * GAS_H;
        const __half* Bs = BsBase + st * GBS_H;
#pragma unroll
        for (int kk = 0; kk < 2; ++kk) {
            uint32_t af[4][4], bfr[2][4];
#pragma unroll
            for (int mt = 0; mt < 4; ++mt)
                ldsm4(af[mt], &As[(wr * 64 + mt * 16 + mrow) * ASTR + kk * 16 + mseg]);
#pragma unroll
            for (int p2 = 0; p2 < 2; ++p2)
                ldsm4t(bfr[p2], &Bs[(kk * 16 + mrow) * BSTR + wc * 32 + p2 * 16 + mseg]);
#pragma unroll
            for (int mt = 0; mt < 4; ++mt)
#pragma unroll
                for (int p2 = 0; p2 < 2; ++p2) {
                    mma16h(acc[mt][2 * p2],     af[mt], bfr[p2][0], bfr[p2][1]);
                    mma16h(acc[mt][2 * p2 + 1], af[mt], bfr[p2][2], bfr[p2][3]);
                }
        }
        st = (st == 2) ? 0 : st + 1;
        wst = (wst == 2) ? 0 : wst + 1;
    }

#pragma unroll
    for (int mt = 0; mt < 4; ++mt) {
        int row0 = by * 128 + wr * 64 + mt * 16 + lr;
#pragma unroll
        for (int nt = 0; nt < 4; ++nt) {
            int col = bx * 128 + wc * 32 + nt * 8 + 2 * lc;
            float2 bv = *(const float2*)(bias + col);
#pragma unroll
            for (int half = 0; half < 2; ++half) {
                int row = row0 + half * 8;
                float v0 = acc[mt][nt][2 * half]     + bv.x;
                float v1 = acc[mt][nt][2 * half + 1] + bv.y;
                if (EPI == 1) { v0 = gelu1(v0); v1 = gelu1(v1); }
                if (EPI == 3 && col < D_MODEL) {
                    // 0.125 * log2(e): softmax runs in base-2 domain
                    v0 *= 0.18033688011112042f; v1 *= 0.18033688011112042f;
                }
                size_t base = (size_t)row * N + col;
                *(__half2*)(C + base) = __floats2half2_rn(v0, v1);
            }
        }
    }
}

// ---------------- FP16 GEMM 64x128 (bias + fp32 residual -> fp32) ------------
#define A64STR 40
#define B64STR 136
__global__ __launch_bounds__(256, 3) void k_gemm64(
    int M, int N, int K,
    const __half* __restrict__ A, const __half* __restrict__ B,
    const float* __restrict__ bias, const float* __restrict__ res,
    float* __restrict__ C)
{
    __shared__ __half As[3][64 * A64STR];
    __shared__ __half Bs[3][32 * B64STR];

    const int tid  = threadIdx.x;
    const int wid  = tid >> 5, lane = tid & 31;
    const int wr   = wid >> 2, wc   = wid & 3;       // warp = 32x32
    const int lr   = lane >> 2, lc  = lane & 3;
    const int bx   = blockIdx.x, by = blockIdx.y;

    const int mrow = ((lane >> 3) & 1) * 8 + (lane & 7);
    const int mseg = (lane >> 4) * 8;

    const int am = tid >> 2, ac = (tid & 3) * 8;     // A: 64 rows x 4 segs
    const int bk = tid >> 3, bc = (tid & 7) * 16;    // B: 32 rows x 2 segs

    const __half* Ab = A + (size_t)(by * 64) * K;
    const __half* Bb = B + bx * 128;

    float acc[2][4][4];
#pragma unroll
    for (int i = 0; i < 2; i++)
#pragma unroll
        for (int j = 0; j < 4; j++)
#pragma unroll
            for (int q = 0; q < 4; q++) acc[i][j][q] = 0.f;

    const int nk = K >> 5;

#pragma unroll
    for (int p = 0; p < 2; ++p) {
        const int k0 = p << 5;
        cp16(&As[p][am * A64STR + ac],  Ab + (size_t)am * K + k0 + ac);
        cp16(&Bs[p][bk * B64STR + bc],     Bb + (size_t)(k0 + bk) * N + bc);
        cp16(&Bs[p][bk * B64STR + bc + 8], Bb + (size_t)(k0 + bk) * N + bc + 8);
        cp_commit();
    }

    int st = 0, wst = 2;
    for (int kt = 0; kt < nk; ++kt) {
        if (kt + 1 < nk) cp_wait<1>(); else cp_wait<0>();
        __syncthreads();
        if (kt + 2 < nk) {
            const int k0 = (kt + 2) << 5;
            cp16(&As[wst][am * A64STR + ac],  Ab + (size_t)am * K + k0 + ac);
            cp16(&Bs[wst][bk * B64STR + bc],     Bb + (size_t)(k0 + bk) * N + bc);
            cp16(&Bs[wst][bk * B64STR + bc + 8], Bb + (size_t)(k0 + bk) * N + bc + 8);
            cp_commit();
        }

#pragma unroll
        for (int kk = 0; kk < 2; ++kk) {
            uint32_t af[2][4], bfr[2][4];
#pragma unroll
            for (int mt = 0; mt < 2; ++mt)
                ldsm4(af[mt], &As[st][(wr * 32 + mt * 16 + mrow) * A64STR + kk * 16 + mseg]);
#pragma unroll
            for (int p2 = 0; p2 < 2; ++p2)
                ldsm4t(bfr[p2], &Bs[st][(kk * 16 + mrow) * B64STR + wc * 32 + p2 * 16 + mseg]);
#pragma unroll
            for (int mt = 0; mt < 2; ++mt)
#pragma unroll
                for (int p2 = 0; p2 < 2; ++p2) {
                    mma16h(acc[mt][2 * p2],     af[mt], bfr[p2][0], bfr[p2][1]);
                    mma16h(acc[mt][2 * p2 + 1], af[mt], bfr[p2][2], bfr[p2][3]);
                }
        }
        st = (st == 2) ? 0 : st + 1;
        wst = (wst == 2) ? 0 : wst + 1;
    }

#pragma unroll
    for (int mt = 0; mt < 2; ++mt) {
        int row0 = by * 64 + wr * 32 + mt * 16 + lr;
#pragma unroll
        for (int nt = 0; nt < 4; ++nt) {
            int col = bx * 128 + wc * 32 + nt * 8 + 2 * lc;
            float2 bv = *(const float2*)(bias + col);
#pragma unroll
            for (int half = 0; half < 2; ++half) {
                int row = row0 + half * 8;
                size_t base = (size_t)row * N + col;
                float2 rv = *(const float2*)(res + base);
                float v0 = acc[mt][nt][2 * half]     + bv.x + rv.x;
                float v1 = acc[mt][nt][2 * half + 1] + bv.y + rv.y;
                *(float2*)(C + base) = make_float2(v0, v1);
            }
        }
    }
}

// ---------------- FP16 flash attention (split-key warps, 3 CTA/SM) -----------
// q-tile 64 rows, 8 warps: warp w covers q-rows (w&3)*16, key-half (w>>2).
// No-max base-2 softmax => halves combine exactly: O=(OA+OB)/(lA+lB).
#define KSTR 72
#define AQ_E (64 * KSTR)
#define KS_E (64 * KSTR)
#define ATTN_SMEM ((AQ_E + 6 * KS_E) * 2)

__global__ __launch_bounds__(256, 3) void k_attn(
    const __half* __restrict__ qkv, __half* __restrict__ out)
{
    extern __shared__ __half smh[];
    __half* Qs = smh;                   // 64 x 72
    __half* Ks = smh + AQ_E;            // 3 x 64 x 72
    __half* Vs = smh + AQ_E + 3 * KS_E; // 3 x 64 x 72

    const int h   = blockIdx.y;
    const int q0  = blockIdx.x * 64;
    const int tid = threadIdx.x;
    const int w   = tid >> 5, lane = tid & 31;
    const int wq  = w & 3;          // q-row group
    const int kh  = w >> 2;         // key half (0/1)
    const int lr  = lane >> 2, lc = lane & 3;

    const int mrow = ((lane >> 3) & 1) * 8 + (lane & 7);
    const int mseg = (lane >> 4) * 8;

    // stage Q (already scaled + fp16 in qkv): 64 rows
#pragma unroll
    for (int i = tid; i < 64 * 8; i += 256) {
        int r = i >> 3, seg = (i & 7) * 8;
        *(uint4*)&Qs[r * KSTR + seg] =
            *(const uint4*)(qkv + (size_t)(q0 + r) * D3 + h * DHEAD + seg);
    }

    // prefetch K/V tiles 0 and 1
#pragma unroll
    for (int p = 0; p < 2; ++p) {
#pragma unroll
        for (int i = tid; i < 64 * 8; i += 256) {
            int r = i >> 3, seg = (i & 7) * 8;
            const __half* base = qkv + (size_t)(p * 64 + r) * D3 + h * DHEAD + seg;
            cp16(&Ks[p * KS_E + r * KSTR + seg], base + D_MODEL);
            cp16(&Vs[p * KS_E + r * KSTR + seg], base + 2 * D_MODEL);
        }
        cp_commit();
    }
    __syncthreads();

    const __half* Qw = Qs + (wq * 16 + mrow) * KSTR;

    float o[8][4];
#pragma unroll
    for (int nt = 0; nt < 8; ++nt)
#pragma unroll
        for (int q = 0; q < 4; ++q) o[nt][q] = 0.f;
    float l_lo = 0.f, l_hi = 0.f;

    const int nkt = N_TOK / 64;
    int st = 0, wst = 2;

    for (int kt0 = 0; kt0 < nkt; ++kt0) {
        if (kt0 + 1 < nkt) cp_wait<1>(); else cp_wait<0>();
        __syncthreads();
        if (kt0 + 2 < nkt) {
            const int tok0 = (kt0 + 2) * 64;
#pragma unroll
            for (int i = tid; i < 64 * 8; i += 256) {
                int r = i >> 3, seg = (i & 7) * 8;
                const __half* base =
                    qkv + (size_t)(tok0 + r) * D3 + h * DHEAD + seg;
                cp16(&Ks[wst * KS_E + r * KSTR + seg], base + D_MODEL);
                cp16(&Vs[wst * KS_E + r * KSTR + seg], base + 2 * D_MODEL);
            }
            cp_commit();
        }

        const __half* KsB = Ks + st * KS_E;
        const __half* VsB = Vs + st * KS_E;

        // two 16-key groups from this warp's key-half
#pragma unroll
        for (int p = 0; p < 2; ++p) {
            const int g = kh * 2 + p;
            float s0[4] = {0.f, 0.f, 0.f, 0.f};
            float s1[4] = {0.f, 0.f, 0.f, 0.f};
#pragma unroll
            for (int kt = 0; kt < 4; ++kt) {
                uint32_t qf[4], kf[4];
                ldsm4(qf, Qw + kt * 16 + mseg);
                ldsm4(kf, &KsB[(g * 16 + mrow) * KSTR + kt * 16 + mseg]);
                mma16h(s0, qf, kf[0], kf[2]);
                mma16h(s1, qf, kf[1], kf[3]);
            }
            float e0 = fexp2(s0[0]), e1 = fexp2(s0[1]);
            float e2 = fexp2(s0[2]), e3 = fexp2(s0[3]);
            float e4 = fexp2(s1[0]), e5 = fexp2(s1[1]);
            float e6 = fexp2(s1[2]), e7 = fexp2(s1[3]);
            l_lo += (e0 + e1) + (e4 + e5);
            l_hi += (e2 + e3) + (e6 + e7);
            uint32_t pf[4];
            pf[0] = h2_as_u32(__floats2half2_rn(e0, e1));
            pf[1] = h2_as_u32(__floats2half2_rn(e2, e3));
            pf[2] = h2_as_u32(__floats2half2_rn(e4, e5));
            pf[3] = h2_as_u32(__floats2half2_rn(e6, e7));
#pragma unroll
            for (int c = 0; c < 4; ++c) {
                uint32_t vf[4];
                ldsm4t(vf, &VsB[(g * 16 + mrow) * KSTR + c * 16 + mseg]);
                mma16h(o[2 * c],     pf, vf[0], vf[1]);
                mma16h(o[2 * c + 1], pf, vf[2], vf[3]);
            }
        }

        st = (st == 2) ? 0 : st + 1;
        wst = (wst == 2) ? 0 : wst + 1;
    }

    // combine key-halves through smem (Ks region dead; cp.async drained)
    __syncthreads();
    float* sm2 = (float*)Ks;            // 4 warps x 32 lanes x 34 floats
    if (kh == 1) {
        float* dst = sm2 + (wq * 32 + lane) * 34;
#pragma unroll
        for (int nt = 0; nt < 8; ++nt) {
            dst[nt * 4 + 0] = o[nt][0]; dst[nt * 4 + 1] = o[nt][1];
            dst[nt * 4 + 2] = o[nt][2]; dst[nt * 4 + 3] = o[nt][3];
        }
        dst[32] = l_lo; dst[33] = l_hi;
    }
    __syncthreads();
    if (kh == 0) {
        const float* src = sm2 + (wq * 32 + lane) * 34;
#pragma unroll
        for (int nt = 0; nt < 8; ++nt) {
            o[nt][0] += src[nt * 4 + 0]; o[nt][1] += src[nt * 4 + 1];
            o[nt][2] += src[nt * 4 + 2]; o[nt][3] += src[nt * 4 + 3];
        }
        l_lo += src[32]; l_hi += src[33];
#pragma unroll
        for (int off = 1; off < 4; off <<= 1) {
            l_lo += __shfl_xor_sync(0xffffffffu, l_lo, off);
            l_hi += __shfl_xor_sync(0xffffffffu, l_hi, off);
        }
        float inv_lo = 1.f / l_lo, inv_hi = 1.f / l_hi;
        int row = q0 + wq * 16 + lr;
#pragma unroll
        for (int nt = 0; nt < 8; ++nt) {
            int col = h * DHEAD + nt * 8 + 2 * lc;
            *(__half2*)(out + (size_t)row * D_MODEL + col) =
                __floats2half2_rn(o[nt][0] * inv_lo, o[nt][1] * inv_lo);
            *(__half2*)(out + (size_t)(row + 8) * D_MODEL + col) =
                __floats2half2_rn(o[nt][2] * inv_hi, o[nt][3] * inv_hi);
        }
    }
}

// ---------------- PEGH ----------------
__global__ void k_pegh_init(int* cellmap, int* pmin) {
    int i = blockIdx.x * blockDim.x + threadIdx.x;
    if (i < GRID_SZ * GRID_SZ) cellmap[i] = -1;
    if (i < 2) pmin[i] = 0x7fffffff;
}

__global__ void k_pos_min(const int* __restrict__ pos, int* pmin) {
    int i = blockIdx.x * blockDim.x + threadIdx.x;
    if (i < N_TOK) {
        atomicMin(&pmin[0], pos[2 * i]);
        atomicMin(&pmin[1], pos[2 * i + 1]);
    }
}

__global__ void k_cellmap(const int* __restrict__ pos, const int* __restrict__ pmin,
                          int* __restrict__ cellmap) {
    int i = blockIdx.x * blockDim.x + threadIdx.x;
    if (i < N_TOK) {
        int p0 = pos[2 * i] - pmin[0];
        int p1 = pos[2 * i + 1] - pmin[1];
        cellmap[p0 * GRID_SZ + p1] = i;
    }
}

__global__ __launch_bounds__(128) void k_pegh(
    const float* __restrict__ x, const int* __restrict__ pos,
    const int* __restrict__ pmin, const int* __restrict__ cellmap,
    const float* __restrict__ cw, const float* __restrict__ cb,
    float* __restrict__ out)
{
    int i = blockIdx.x;
    int t = threadIdx.x;
    __shared__ int nb[9];
    __shared__ float sred[4];
    __shared__ float stot;

    int p0 = pos[2 * i] - pmin[0];
    int p1 = pos[2 * i + 1] - pmin[1];
    if (t < 9) {
        int dj = t % 3 - 1;
        int di = t / 3 - 1;
        int a = p0 + dj, b2 = p1 + di;
        nb[t] = (a >= 0 && a < GRID_SZ && b2 >= 0 && b2 < GRID_SZ)
                    ? cellmap[a * GRID_SZ + b2] : -1;
    }

    const float* xr = x + (size_t)i * D_MODEL;
    float s = 0.f;
    for (int c = t; c < D_MODEL; c += 128) s += xr[c];
    s = warp_sum(s);
    int w = t >> 5, lane = t & 31;
    if (lane == 0) sred[w] = s;
    __syncthreads();
    if (t == 0) stot = sred[0] + sred[1] + sred[2] + sred[3];
    __syncthreads();
    bool mask = (stot != 0.0f);

    for (int c = t; c < D_MODEL; c += 128) {
        float v = xr[c];
        if (mask) {
            float a = cb[c];
#pragma unroll
            for (int k = 0; k < 9; k++) {
                int p = nb[k];
                if (p >= 0) a = fmaf(cw[c * 9 + k], x[(size_t)p * D_MODEL + c], a);
            }
            v += a;
        }
        out[(size_t)i * D_MODEL + c] = v;
    }
}

// ---------------- host-side orchestration ----------------
static void run_block(const float* xin, float* xout, int l,
                      const __half* Wqkv, const float* bqkv,
                      const __half* Wo, const float* bo,
                      const float* ln1g, const float* ln1b,
                      const __half* W1, const float* b1,
                      const __half* W2, const float* b2,
                      const float* ln2g, const float* ln2b,
                      __half* h, __half* qkv, __half* ao, float* xa, __half* mlp)
{
    k_layernorm<1><<<N_TOK, 128>>>(xin, ln1g + l * D_MODEL, ln1b + l * D_MODEL, h);
    k_gemm<3><<<dim3(D3 / 128, N_TOK / 128), 256, GEMM_SMEM>>>(
        N_TOK, D3, D_MODEL, h, Wqkv + (size_t)l * D_MODEL * D3,
        bqkv + l * D3, qkv);
    k_attn<<<dim3(N_TOK / 64, HEADS), 256, ATTN_SMEM>>>(qkv, ao);
    k_gemm64<<<dim3(D_MODEL / 128, N_TOK / 64), 256>>>(
        N_TOK, D_MODEL, D_MODEL, ao, Wo + (size_t)l * D_MODEL * D_MODEL,
        bo + l * D_MODEL, xin, xa);
    k_layernorm<1><<<N_TOK, 128>>>(xa, ln2g + l * D_MODEL, ln2b + l * D_MODEL, h);
    k_gemm<1><<<dim3(MLP_DIM / 128, N_TOK / 128), 256, GEMM_SMEM>>>(
        N_TOK, MLP_DIM, D_MODEL, h, W1 + (size_t)l * D_MODEL * MLP_DIM,
        b1 + l * MLP_DIM, mlp);
    k_gemm64<<<dim3(D_MODEL / 128, N_TOK / 64), 256>>>(
        N_TOK, D_MODEL, MLP_DIM, mlp, W2 + (size_t)l * MLP_DIM * D_MODEL,
        b2 + l * D_MODEL, xa, xout);
}

extern "C" void kernel_launch(void* const* d_in, const int* in_sizes, int n_in,
                              void* d_out, int out_size)
{
    (void)in_sizes; (void)n_in; (void)out_size;
    const float* x     = (const float*)d_in[0];
    const int*   pos   = (const int*)  d_in[1];
    const float* Wqkv  = (const float*)d_in[2];
    const float* bqkv  = (const float*)d_in[3];
    const float* Wo    = (const float*)d_in[4];
    const float* bo    = (const float*)d_in[5];
    const float* ln1g  = (const float*)d_in[6];
    const float* ln1b  = (const float*)d_in[7];
    const float* W1    = (const float*)d_in[8];
    const float* b1    = (const float*)d_in[9];
    const float* W2    = (const float*)d_in[10];
    const float* b2    = (const float*)d_in[11];
    const float* ln2g  = (const float*)d_in[12];
    const float* ln2b  = (const float*)d_in[13];
    const float* convw = (const float*)d_in[14];
    const float* convb = (const float*)d_in[15];
    const float* normg = (const float*)d_in[16];
    const float* normb = (const float*)d_in[17];
    float* out = (float*)d_out;

    float *xa, *x1, *x2, *wcf;
    __half *h, *qkv, *ao, *mlp;
    int *cellmap, *pmin;
    cudaGetSymbolAddress((void**)&h,   g_h);
    cudaGetSymbolAddress((void**)&qkv, g_qkv);
    cudaGetSymbolAddress((void**)&ao,  g_ao);
    cudaGetSymbolAddress((void**)&xa,  g_xa);
    cudaGetSymbolAddress((void**)&x1,  g_x1);
    cudaGetSymbolAddress((void**)&x2,  g_x2);
    cudaGetSymbolAddress((void**)&mlp, g_mlp);
    cudaGetSymbolAddress((void**)&wcf, g_wc);
    cudaGetSymbolAddress((void**)&cellmap, g_cellmap);
    cudaGetSymbolAddress((void**)&pmin,    g_pmin);
    __half* wh = (__half*)wcf;

    cudaFuncSetAttribute(k_attn, cudaFuncAttributeMaxDynamicSharedMemorySize,
                         ATTN_SMEM);
    cudaFuncSetAttribute(k_gemm<1>, cudaFuncAttributeMaxDynamicSharedMemorySize,
                         GEMM_SMEM);
    cudaFuncSetAttribute(k_gemm<3>, cudaFuncAttributeMaxDynamicSharedMemorySize,
                         GEMM_SMEM);

    // pre-convert all weights to fp16 in one launch
    __half* wqkv_h = wh;
    __half* wo_h   = wh + WQKV_SZ;
    __half* w1_h   = wh + WQKV_SZ + WO_SZ;
    __half* w2_h   = wh + WQKV_SZ + WO_SZ + W1_SZ;
    k_cvt4<<<(WTOT_SZ / 4 + 255) / 256, 256>>>(Wqkv, Wo, W1, W2, wh);

    // layer 0: x -> x1
    run_block(x, x1, 0, wqkv_h, bqkv, wo_h, bo, ln1g, ln1b, w1_h, b1, w2_h, b2,
              ln2g, ln2b, h, qkv, ao, xa, mlp);

    // PEGH: x1 -> x2
    k_pegh_init<<<(GRID_SZ * GRID_SZ + 127) / 128, 128>>>(cellmap, pmin);
    k_pos_min<<<N_TOK / 128, 128>>>(pos, pmin);
    k_cellmap<<<N_TOK / 128, 128>>>(pos, pmin, cellmap);
    k_pegh<<<N_TOK, 128>>>(x1, pos, pmin, cellmap, convw, convb, x2);

    // layer 1: x2 -> x1
    run_block(x2, x1, 1, wqkv_h, bqkv, wo_h, bo, ln1g, ln1b, w1_h, b1, w2_h, b2,
              ln2g, ln2b, h, qkv, ao, xa, mlp);

    // final LN -> out
    k_layernorm<0><<<N_TOK, 128>>>(x1, normg, normb, out);
}

// round 17
// speedup vs baseline: 1.1139x; 1.1139x over previous
#include <cuda_runtime.h>
#include <cuda_fp16.h>
#include <math.h>
#include <stdint.h>

#define N_TOK   4096
#define D_MODEL 512
#define D3      1536
#define MLP_DIM 2048
#define HEADS   8
#define DHEAD   64
#define GRID_SZ 80

// ---------------- scratch (no allocations allowed) ----------------
__device__ float g_h  [N_TOK * D_MODEL];   // used as __half
__device__ float g_qkv[N_TOK * D3];        // used as __half
__device__ float g_ao [N_TOK * D_MODEL];   // used as __half
__device__ float g_xa [N_TOK * D_MODEL];
__device__ float g_x1 [N_TOK * D_MODEL];
__device__ float g_x2 [N_TOK * D_MODEL];
__device__ float g_mlp[N_TOK * MLP_DIM];   // used as __half
__device__ int   g_cellmap[GRID_SZ * GRID_SZ];
__device__ int   g_pmin[2];

// fp16 pre-converted weights (element counts)
#define WQKV_SZ (2 * D_MODEL * D3)
#define WO_SZ   (2 * D_MODEL * D_MODEL)
#define W1_SZ   (2 * D_MODEL * MLP_DIM)
#define W2_SZ   (2 * MLP_DIM * D_MODEL)
#define WTOT_SZ (WQKV_SZ + WO_SZ + W1_SZ + W2_SZ)
__device__ float g_wc[WTOT_SZ / 2];  // as __half

// ---------------- helpers ----------------
__device__ __forceinline__ uint32_t h2_as_u32(__half2 h) {
    return *(uint32_t*)&h;
}
__device__ __forceinline__ __half2 h2bits(uint32_t u) {
    __half2 h; *(uint32_t*)&h = u; return h;
}

__device__ __forceinline__ float warp_sum(float v) {
#pragma unroll
    for (int o = 16; o > 0; o >>= 1) v += __shfl_xor_sync(0xffffffffu, v, o);
    return v;
}

// fp16 mma m16n8k16, fp32 accum
__device__ __forceinline__ void mma16h(float* d, const uint32_t* a,
                                       uint32_t b0, uint32_t b1) {
    asm volatile(
        "mma.sync.aligned.m16n8k16.row.col.f32.f16.f16.f32 "
        "{%0,%1,%2,%3},{%4,%5,%6,%7},{%8,%9},{%0,%1,%2,%3};"
        : "+f"(d[0]), "+f"(d[1]), "+f"(d[2]), "+f"(d[3])
        : "r"(a[0]), "r"(a[1]), "r"(a[2]), "r"(a[3]), "r"(b0), "r"(b1));
}

__device__ __forceinline__ void ldsm4(uint32_t* r, const void* p) {
    uint32_t a = (uint32_t)__cvta_generic_to_shared(p);
    asm volatile("ldmatrix.sync.aligned.m8n8.x4.shared.b16 {%0,%1,%2,%3}, [%4];"
        : "=r"(r[0]), "=r"(r[1]), "=r"(r[2]), "=r"(r[3]) : "r"(a));
}
__device__ __forceinline__ void ldsm4t(uint32_t* r, const void* p) {
    uint32_t a = (uint32_t)__cvta_generic_to_shared(p);
    asm volatile("ldmatrix.sync.aligned.m8n8.x4.trans.shared.b16 {%0,%1,%2,%3}, [%4];"
        : "=r"(r[0]), "=r"(r[1]), "=r"(r[2]), "=r"(r[3]) : "r"(a));
}

__device__ __forceinline__ void cp16(void* smem, const void* g) {
    uint32_t s = (uint32_t)__cvta_generic_to_shared(smem);
    asm volatile("cp.async.cg.shared.global [%0], [%1], 16;\n" :: "r"(s), "l"(g));
}
__device__ __forceinline__ void cp_commit() { asm volatile("cp.async.commit_group;\n"); }
template <int NcpW> __device__ __forceinline__ void cp_wait() {
    asm volatile("cp.async.wait_group %0;\n" :: "n"(NcpW));
}

// packed half2 2^x for x in ~[-14,14] (clamped); deg-3 poly in HFMA2.
// Magic 1536 rounds to int (fp16 ulp=1 there); exponent applied by per-lane
// bit add: nb = n+16 in [2,30] so (nb&0x1F)<<10 stays inside each 16-bit lane.
__device__ __forceinline__ uint32_t hexp2x2(float a, float b) {
    __half2 h = __floats2half2_rn(a, b);
    h = __hmax2(h, h2bits(0xCB00CB00u));   // -14
    h = __hmin2(h, h2bits(0x4B004B00u));   // +14
    const __half2 M2 = h2bits(0x66006600u);  // 1536
    __half2 z = __hadd2(h, M2);
    __half2 r = __hsub2(z, M2);
    __half2 f = __hsub2(h, r);
    __half2 p = h2bits(0x2B582B58u);                         // 0.05736
    p = __hfma2(p, f, h2bits(0x33AF33AFu));                  // 0.24013
    p = __hfma2(p, f, h2bits(0x398C398Cu));                  // 0.69317
    p = __hfma2(p, f, h2bits(0x3C003C00u));                  // 1.0
    uint32_t nb = h2_as_u32(z) - 0x65F065F0u;                // n+16 per lane
    uint32_t sh = (nb & 0x001F001Fu) << 10;
    return h2_as_u32(p) + sh - 0x40004000u;
}

// ---------------- merged weight fp16 pre-conversion ----------------
__global__ __launch_bounds__(256) void k_cvt4(
    const float* __restrict__ s0, const float* __restrict__ s1,
    const float* __restrict__ s2, const float* __restrict__ s3,
    __half* __restrict__ dst)
{
    int i = (blockIdx.x * 256 + threadIdx.x) << 2;
    if (i >= WTOT_SZ) return;
    const float* src; int off;
    if (i < WQKV_SZ)                         { src = s0; off = 0; }
    else if (i < WQKV_SZ + WO_SZ)            { src = s1; off = WQKV_SZ; }
    else if (i < WQKV_SZ + WO_SZ + W1_SZ)    { src = s2; off = WQKV_SZ + WO_SZ; }
    else                                     { src = s3; off = WQKV_SZ + WO_SZ + W1_SZ; }
    float4 v = *(const float4*)(src + (i - off));
    uint2 o;
    o.x = h2_as_u32(__floats2half2_rn(v.x, v.y));
    o.y = h2_as_u32(__floats2half2_rn(v.z, v.w));
    *(uint2*)(dst + i) = o;
}

// ---------------- LayerNorm ----------------
template <int OUTH>
__global__ __launch_bounds__(128) void k_layernorm(
    const float* __restrict__ x, const float* __restrict__ g,
    const float* __restrict__ b, void* __restrict__ outv)
{
    int row = blockIdx.x;
    const float4* xr = (const float4*)(x + (size_t)row * D_MODEL);
    float4 v = xr[threadIdx.x];
    float s  = v.x + v.y + v.z + v.w;
    float sq = v.x * v.x + v.y * v.y + v.z * v.z + v.w * v.w;

    __shared__ float sh1[4], sh2[4];
    int w = threadIdx.x >> 5, lane = threadIdx.x & 31;
    s = warp_sum(s); sq = warp_sum(sq);
    if (lane == 0) { sh1[w] = s; sh2[w] = sq; }
    __syncthreads();
    float ts = sh1[0] + sh1[1] + sh1[2] + sh1[3];
    float tq = sh2[0] + sh2[1] + sh2[2] + sh2[3];
    float mean = ts * (1.0f / D_MODEL);
    float var  = tq * (1.0f / D_MODEL) - mean * mean;
    float r    = rsqrtf(var + 1e-5f);

    float4 gv = ((const float4*)g)[threadIdx.x];
    float4 bv = ((const float4*)b)[threadIdx.x];
    float4 o;
    o.x = (v.x - mean) * r * gv.x + bv.x;
    o.y = (v.y - mean) * r * gv.y + bv.y;
    o.z = (v.z - mean) * r * gv.z + bv.z;
    o.w = (v.w - mean) * r * gv.w + bv.w;
    if (OUTH) {
        uint2 hh;
        hh.x = h2_as_u32(__floats2half2_rn(o.x, o.y));
        hh.y = h2_as_u32(__floats2half2_rn(o.z, o.w));
        *(uint2*)((__half*)outv + (size_t)row * D_MODEL + threadIdx.x * 4) = hh;
    } else {
        ((float4*)((float*)outv + (size_t)row * D_MODEL))[threadIdx.x] = o;
    }
}

// ---------------- GELU (tanh approx) ----------------
__device__ __forceinline__ float gelu1(float u) {
    return 0.5f * u * (1.0f + tanhf(0.7978845608028654f *
                                    (u + 0.044715f * u * u * u)));
}

// ---------------- FP16 GEMM 128x128, k-tile 32, 3-stage, single-sync ---------
// EPI: 1 bias+gelu -> fp16; 3 bias + (0.125*log2e) Q-scale -> fp16
#define ASTR 40
#define BSTR 136
#define GAS_H (128 * ASTR)
#define GBS_H (32 * BSTR)
#define GEMM_SMEM ((3 * GAS_H + 3 * GBS_H) * 2)

template <int EPI>
__global__ __launch_bounds__(256, 2) void k_gemm(
    int M, int N, int K,
    const __half* __restrict__ A, const __half* __restrict__ B,
    const float* __restrict__ bias, __half* __restrict__ C)
{
    extern __shared__ __half gsmh[];
    __half* AsBase = gsmh;
    __half* BsBase = gsmh + 3 * GAS_H;

    const int tid  = threadIdx.x;
    const int wid  = tid >> 5, lane = tid & 31;
    const int wr   = wid >> 2, wc   = wid & 3;
    const int lr   = lane >> 2, lc  = lane & 3;
    const int bx   = blockIdx.x, by = blockIdx.y;

    const int mrow = ((lane >> 3) & 1) * 8 + (lane & 7);
    const int mseg = (lane >> 4) * 8;

    const int am = tid >> 1, ac = (tid & 1) * 16;
    const int bk = tid >> 3, bc = (tid & 7) * 16;

    const __half* Ab = A + (size_t)(by * 128) * K;
    const __half* Bb = B + bx * 128;

    float acc[4][4][4];
#pragma unroll
    for (int i = 0; i < 4; i++)
#pragma unroll
        for (int j = 0; j < 4; j++)
#pragma unroll
            for (int q = 0; q < 4; q++) acc[i][j][q] = 0.f;

    const int nk = K >> 5;

#pragma unroll
    for (int p = 0; p < 2; ++p) {
        const int k0 = p << 5;
        __half* As = AsBase + p * GAS_H;
        __half* Bs = BsBase + p * GBS_H;
        cp16(&As[am * ASTR + ac],     Ab + (size_t)am * K + k0 + ac);
        cp16(&As[am * ASTR + ac + 8], Ab + (size_t)am * K + k0 + ac + 8);
        cp16(&Bs[bk * BSTR + bc],     Bb + (size_t)(k0 + bk) * N + bc);
        cp16(&Bs[bk * BSTR + bc + 8], Bb + (size_t)(k0 + bk) * N + bc + 8);
        cp_commit();
    }

    int st = 0, wst = 2;
    for (int kt = 0; kt < nk; ++kt) {
        if (kt + 1 < nk) cp_wait<1>(); else cp_wait<0>();
        __syncthreads();
        if (kt + 2 < nk) {
            const int k0 = (kt + 2) << 5;
            __half* As = AsBase + wst * GAS_H;
            __half* Bs = BsBase + wst * GBS_H;
            cp16(&As[am * ASTR + ac],     Ab + (size_t)am * K + k0 + ac);
            cp16(&As[am * ASTR + ac + 8], Ab + (size_t)am * K + k0 + ac + 8);
            cp16(&Bs[bk * BSTR + bc],     Bb + (size_t)(k0 + bk) * N + bc);
            cp16(&Bs[bk * BSTR + bc + 8], Bb + (size_t)(k0 + bk) * N + bc + 8);
            cp_commit();
        }

        const __half* As = AsBase + st * GAS_H;
        const __half* Bs = BsBase + st * GBS_H;
#pragma unroll
        for (int kk = 0; kk < 2; ++kk) {
            uint32_t af[4][4], bfr[2][4];
#pragma unroll
            for (int mt = 0; mt < 4; ++mt)
                ldsm4(af[mt], &As[(wr * 64 + mt * 16 + mrow) * ASTR + kk * 16 + mseg]);
#pragma unroll
            for (int p2 = 0; p2 < 2; ++p2)
                ldsm4t(bfr[p2], &Bs[(kk * 16 + mrow) * BSTR + wc * 32 + p2 * 16 + mseg]);
#pragma unroll
            for (int mt = 0; mt < 4; ++mt)
#pragma unroll
                for (int p2 = 0; p2 < 2; ++p2) {
                    mma16h(acc[mt][2 * p2],     af[mt], bfr[p2][0], bfr[p2][1]);
                    mma16h(acc[mt][2 * p2 + 1], af[mt], bfr[p2][2], bfr[p2][3]);
                }
        }
        st = (st == 2) ? 0 : st + 1;
        wst = (wst == 2) ? 0 : wst + 1;
    }

#pragma unroll
    for (int mt = 0; mt < 4; ++mt) {
        int row0 = by * 128 + wr * 64 + mt * 16 + lr;
#pragma unroll
        for (int nt = 0; nt < 4; ++nt) {
            int col = bx * 128 + wc * 32 + nt * 8 + 2 * lc;
            float2 bv = *(const float2*)(bias + col);
#pragma unroll
            for (int half = 0; half < 2; ++half) {
                int row = row0 + half * 8;
                float v0 = acc[mt][nt][2 * half]     + bv.x;
                float v1 = acc[mt][nt][2 * half + 1] + bv.y;
                if (EPI == 1) { v0 = gelu1(v0); v1 = gelu1(v1); }
                if (EPI == 3 && col < D_MODEL) {
                    v0 *= 0.18033688011112042f; v1 *= 0.18033688011112042f;
                }
                size_t base = (size_t)row * N + col;
                *(__half2*)(C + base) = __floats2half2_rn(v0, v1);
            }
        }
    }
}

// ---------------- FP16 GEMM 64x128 (bias + fp32 residual -> fp32) ------------
#define A64STR 40
#define B64STR 136
__global__ __launch_bounds__(256, 3) void k_gemm64(
    int M, int N, int K,
    const __half* __restrict__ A, const __half* __restrict__ B,
    const float* __restrict__ bias, const float* __restrict__ res,
    float* __restrict__ C)
{
    __shared__ __half As[3][64 * A64STR];
    __shared__ __half Bs[3][32 * B64STR];

    const int tid  = threadIdx.x;
    const int wid  = tid >> 5, lane = tid & 31;
    const int wr   = wid >> 2, wc   = wid & 3;
    const int lr   = lane >> 2, lc  = lane & 3;
    const int bx   = blockIdx.x, by = blockIdx.y;

    const int mrow = ((lane >> 3) & 1) * 8 + (lane & 7);
    const int mseg = (lane >> 4) * 8;

    const int am = tid >> 2, ac = (tid & 3) * 8;
    const int bk = tid >> 3, bc = (tid & 7) * 16;

    const __half* Ab = A + (size_t)(by * 64) * K;
    const __half* Bb = B + bx * 128;

    float acc[2][4][4];
#pragma unroll
    for (int i = 0; i < 2; i++)
#pragma unroll
        for (int j = 0; j < 4; j++)
#pragma unroll
            for (int q = 0; q < 4; q++) acc[i][j][q] = 0.f;

    const int nk = K >> 5;

#pragma unroll
    for (int p = 0; p < 2; ++p) {
        const int k0 = p << 5;
        cp16(&As[p][am * A64STR + ac],  Ab + (size_t)am * K + k0 + ac);
        cp16(&Bs[p][bk * B64STR + bc],     Bb + (size_t)(k0 + bk) * N + bc);
        cp16(&Bs[p][bk * B64STR + bc + 8], Bb + (size_t)(k0 + bk) * N + bc + 8);
        cp_commit();
    }

    int st = 0, wst = 2;
    for (int kt = 0; kt < nk; ++kt) {
        if (kt + 1 < nk) cp_wait<1>(); else cp_wait<0>();
        __syncthreads();
        if (kt + 2 < nk) {
            const int k0 = (kt + 2) << 5;
            cp16(&As[wst][am * A64STR + ac],  Ab + (size_t)am * K + k0 + ac);
            cp16(&Bs[wst][bk * B64STR + bc],     Bb + (size_t)(k0 + bk) * N + bc);
            cp16(&Bs[wst][bk * B64STR + bc + 8], Bb + (size_t)(k0 + bk) * N + bc + 8);
            cp_commit();
        }

#pragma unroll
        for (int kk = 0; kk < 2; ++kk) {
            uint32_t af[2][4], bfr[2][4];
#pragma unroll
            for (int mt = 0; mt < 2; ++mt)
                ldsm4(af[mt], &As[st][(wr * 32 + mt * 16 + mrow) * A64STR + kk * 16 + mseg]);
#pragma unroll
            for (int p2 = 0; p2 < 2; ++p2)
                ldsm4t(bfr[p2], &Bs[st][(kk * 16 + mrow) * B64STR + wc * 32 + p2 * 16 + mseg]);
#pragma unroll
            for (int mt = 0; mt < 2; ++mt)
#pragma unroll
                for (int p2 = 0; p2 < 2; ++p2) {
                    mma16h(acc[mt][2 * p2],     af[mt], bfr[p2][0], bfr[p2][1]);
                    mma16h(acc[mt][2 * p2 + 1], af[mt], bfr[p2][2], bfr[p2][3]);
                }
        }
        st = (st == 2) ? 0 : st + 1;
        wst = (wst == 2) ? 0 : wst + 1;
    }

#pragma unroll
    for (int mt = 0; mt < 2; ++mt) {
        int row0 = by * 64 + wr * 32 + mt * 16 + lr;
#pragma unroll
        for (int nt = 0; nt < 4; ++nt) {
            int col = bx * 128 + wc * 32 + nt * 8 + 2 * lc;
            float2 bv = *(const float2*)(bias + col);
#pragma unroll
            for (int half = 0; half < 2; ++half) {
                int row = row0 + half * 8;
                size_t base = (size_t)row * N + col;
                float2 rv = *(const float2*)(res + base);
                float v0 = acc[mt][nt][2 * half]     + bv.x + rv.x;
                float v1 = acc[mt][nt][2 * half + 1] + bv.y + rv.y;
                *(float2*)(C + base) = make_float2(v0, v1);
            }
        }
    }
}

// ---------------- FP16 flash attention (half2 softmax, l via ones-mma) -------
// Q pre-scaled by 0.125*log2e; P = 2^S / sum 2^S == e-base softmax exactly.
#define KSTR 72
#define QS_E (128 * KSTR)
#define KS_E (64 * KSTR)
#define ATTN_SMEM ((QS_E + 6 * KS_E) * 2)

__global__ __launch_bounds__(256, 2) void k_attn(
    const __half* __restrict__ qkv, __half* __restrict__ out)
{
    extern __shared__ __half smh[];
    __half* Qs = smh;                   // 128 x 72
    __half* Ks = smh + QS_E;            // 3 x 64 x 72
    __half* Vs = smh + QS_E + 3 * KS_E; // 3 x 64 x 72

    const int h   = blockIdx.y;
    const int q0  = blockIdx.x * 128;
    const int tid = threadIdx.x;
    const int wq  = tid >> 5, lane = tid & 31;
    const int lr  = lane >> 2, lc = lane & 3;

    const int mrow = ((lane >> 3) & 1) * 8 + (lane & 7);
    const int mseg = (lane >> 4) * 8;

    // ones B-fragment (column n=0 all ones) for l accumulation via mma
    const uint32_t bones = (lane < 4) ? 0x3C003C00u : 0u;

    // stage Q (already scaled + fp16 in qkv)
#pragma unroll
    for (int i = tid; i < 128 * 8; i += 256) {
        int r = i >> 3, seg = (i & 7) * 8;
        *(uint4*)&Qs[r * KSTR + seg] =
            *(const uint4*)(qkv + (size_t)(q0 + r) * D3 + h * DHEAD + seg);
    }

    // prefetch K/V tiles 0 and 1
#pragma unroll
    for (int p = 0; p < 2; ++p) {
#pragma unroll
        for (int i = tid; i < 64 * 8; i += 256) {
            int r = i >> 3, seg = (i & 7) * 8;
            const __half* base = qkv + (size_t)(p * 64 + r) * D3 + h * DHEAD + seg;
            cp16(&Ks[p * KS_E + r * KSTR + seg], base + D_MODEL);
            cp16(&Vs[p * KS_E + r * KSTR + seg], base + 2 * D_MODEL);
        }
        cp_commit();
    }
    __syncthreads();

    uint32_t qf[4][4];
    {
        int rb = wq * 16;
#pragma unroll
        for (int kt = 0; kt < 4; ++kt)
            ldsm4(qf[kt], &Qs[(rb + mrow) * KSTR + kt * 16 + mseg]);
    }

    float o[8][4];
#pragma unroll
    for (int nt = 0; nt < 8; ++nt)
#pragma unroll
        for (int q = 0; q < 4; ++q) o[nt][q] = 0.f;
    float lacc[4] = {0.f, 0.f, 0.f, 0.f};

    const int nkt = N_TOK / 64;
    int st = 0, wst = 2;

    for (int kt0 = 0; kt0 < nkt; ++kt0) {
        if (kt0 + 1 < nkt) cp_wait<1>(); else cp_wait<0>();
        __syncthreads();
        if (kt0 + 2 < nkt) {
            const int tok0 = (kt0 + 2) * 64;
#pragma unroll
            for (int i = tid; i < 64 * 8; i += 256) {
                int r = i >> 3, seg = (i & 7) * 8;
                const __half* base =
                    qkv + (size_t)(tok0 + r) * D3 + h * DHEAD + seg;
                cp16(&Ks[wst * KS_E + r * KSTR + seg], base + D_MODEL);
                cp16(&Vs[wst * KS_E + r * KSTR + seg], base + 2 * D_MODEL);
            }
            cp_commit();
        }

        const __half* KsB = Ks + st * KS_E;
        const __half* VsB = Vs + st * KS_E;

        // four 16-key group pipelines
#pragma unroll
        for (int p = 0; p < 4; ++p) {
            float s0[4] = {0.f, 0.f, 0.f, 0.f};
            float s1[4] = {0.f, 0.f, 0.f, 0.f};
#pragma unroll
            for (int kt = 0; kt < 4; ++kt) {
                uint32_t kf[4];
                ldsm4(kf, &KsB[(p * 16 + mrow) * KSTR + kt * 16 + mseg]);
                mma16h(s0, qf[kt], kf[0], kf[2]);
                mma16h(s1, qf[kt], kf[1], kf[3]);
            }
            // P = 2^S directly in half2 (A-fragment layout)
            uint32_t pf[4];
            pf[0] = hexp2x2(s0[0], s0[1]);
            pf[1] = hexp2x2(s0[2], s0[3]);
            pf[2] = hexp2x2(s1[0], s1[1]);
            pf[3] = hexp2x2(s1[2], s1[3]);
            // l += P @ ones  (col 0 of lacc holds row sums)
            mma16h(lacc, pf, bones, bones);
#pragma unroll
            for (int c = 0; c < 4; ++c) {
                uint32_t vf[4];
                ldsm4t(vf, &VsB[(p * 16 + mrow) * KSTR + c * 16 + mseg]);
                mma16h(o[2 * c],     pf, vf[0], vf[1]);
                mma16h(o[2 * c + 1], pf, vf[2], vf[3]);
            }
        }

        st = (st == 2) ? 0 : st + 1;
        wst = (wst == 2) ? 0 : wst + 1;
    }

    // finalize: l sits in lacc[0]/lacc[2] at col 2*lc (nonzero only lc==0);
    // quad shuffle-sum recovers full row sums, then normalize.
    float l_lo = lacc[0], l_hi = lacc[2];
#pragma unroll
    for (int off = 1; off < 4; off <<= 1) {
        l_lo += __shfl_xor_sync(0xffffffffu, l_lo, off);
        l_hi += __shfl_xor_sync(0xffffffffu, l_hi, off);
    }
    float inv_lo = 1.f / l_lo, inv_hi = 1.f / l_hi;
    int row = q0 + wq * 16 + lr;
#pragma unroll
    for (int nt = 0; nt < 8; ++nt) {
        int col = h * DHEAD + nt * 8 + 2 * lc;
        *(__half2*)(out + (size_t)row * D_MODEL + col) =
            __floats2half2_rn(o[nt][0] * inv_lo, o[nt][1] * inv_lo);
        *(__half2*)(out + (size_t)(row + 8) * D_MODEL + col) =
            __floats2half2_rn(o[nt][2] * inv_hi, o[nt][3] * inv_hi);
    }
}

// ---------------- PEGH ----------------
__global__ void k_pegh_init(int* cellmap, int* pmin) {
    int i = blockIdx.x * blockDim.x + threadIdx.x;
    if (i < GRID_SZ * GRID_SZ) cellmap[i] = -1;
    if (i < 2) pmin[i] = 0x7fffffff;
}

__global__ void k_pos_min(const int* __restrict__ pos, int* pmin) {
    int i = blockIdx.x * blockDim.x + threadIdx.x;
    if (i < N_TOK) {
        atomicMin(&pmin[0], pos[2 * i]);
        atomicMin(&pmin[1], pos[2 * i + 1]);
    }
}

__global__ void k_cellmap(const int* __restrict__ pos, const int* __restrict__ pmin,
                          int* __restrict__ cellmap) {
    int i = blockIdx.x * blockDim.x + threadIdx.x;
    if (i < N_TOK) {
        int p0 = pos[2 * i] - pmin[0];
        int p1 = pos[2 * i + 1] - pmin[1];
        cellmap[p0 * GRID_SZ + p1] = i;
    }
}

__global__ __launch_bounds__(128) void k_pegh(
    const float* __restrict__ x, const int* __restrict__ pos,
    const int* __restrict__ pmin, const int* __restrict__ cellmap,
    const float* __restrict__ cw, const float* __restrict__ cb,
    float* __restrict__ out)
{
    int i = blockIdx.x;
    int t = threadIdx.x;
    __shared__ int nb[9];
    __shared__ float sred[4];
    __shared__ float stot;

    int p0 = pos[2 * i] - pmin[0];
    int p1 = pos[2 * i + 1] - pmin[1];
    if (t < 9) {
        int dj = t % 3 - 1;
        int di = t / 3 - 1;
        int a = p0 + dj, b2 = p1 + di;
        nb[t] = (a >= 0 && a < GRID_SZ && b2 >= 0 && b2 < GRID_SZ)
                    ? cellmap[a * GRID_SZ + b2] : -1;
    }

    const float* xr = x + (size_t)i * D_MODEL;
    float s = 0.f;
    for (int c = t; c < D_MODEL; c += 128) s += xr[c];
    s = warp_sum(s);
    int w = t >> 5, lane = t & 31;
    if (lane == 0) sred[w] = s;
    __syncthreads();
    if (t == 0) stot = sred[0] + sred[1] + sred[2] + sred[3];
    __syncthreads();
    bool mask = (stot != 0.0f);

    for (int c = t; c < D_MODEL; c += 128) {
        float v = xr[c];
        if (mask) {
            float a = cb[c];
#pragma unroll
            for (int k = 0; k < 9; k++) {
                int p = nb[k];
                if (p >= 0) a = fmaf(cw[c * 9 + k], x[(size_t)p * D_MODEL + c], a);
            }
            v += a;
        }
        out[(size_t)i * D_MODEL + c] = v;
    }
}

// ---------------- host-side orchestration ----------------
static void run_block(const float* xin, float* xout, int l,
                      const __half* Wqkv, const float* bqkv,
                      const __half* Wo, const float* bo,
                      const float* ln1g, const float* ln1b,
                      const __half* W1, const float* b1,
                      const __half* W2, const float* b2,
                      const float* ln2g, const float* ln2b,
                      __half* h, __half* qkv, __half* ao, float* xa, __half* mlp)
{
    k_layernorm<1><<<N_TOK, 128>>>(xin, ln1g + l * D_MODEL, ln1b + l * D_MODEL, h);
    k_gemm<3><<<dim3(D3 / 128, N_TOK / 128), 256, GEMM_SMEM>>>(
        N_TOK, D3, D_MODEL, h, Wqkv + (size_t)l * D_MODEL * D3,
        bqkv + l * D3, qkv);
    k_attn<<<dim3(N_TOK / 128, HEADS), 256, ATTN_SMEM>>>(qkv, ao);
    k_gemm64<<<dim3(D_MODEL / 128, N_TOK / 64), 256>>>(
        N_TOK, D_MODEL, D_MODEL, ao, Wo + (size_t)l * D_MODEL * D_MODEL,
        bo + l * D_MODEL, xin, xa);
    k_layernorm<1><<<N_TOK, 128>>>(xa, ln2g + l * D_MODEL, ln2b + l * D_MODEL, h);
    k_gemm<1><<<dim3(MLP_DIM / 128, N_TOK / 128), 256, GEMM_SMEM>>>(
        N_TOK, MLP_DIM, D_MODEL, h, W1 + (size_t)l * D_MODEL * MLP_DIM,
        b1 + l * MLP_DIM, mlp);
    k_gemm64<<<dim3(D_MODEL / 128, N_TOK / 64), 256>>>(
        N_TOK, D_MODEL, MLP_DIM, mlp, W2 + (size_t)l * MLP_DIM * D_MODEL,
        b2 + l * D_MODEL, xa, xout);
}

extern "C" void kernel_launch(void* const* d_in, const int* in_sizes, int n_in,
                              void* d_out, int out_size)
{
    (void)in_sizes; (void)n_in; (void)out_size;
    const float* x     = (const float*)d_in[0];
    const int*   pos   = (const int*)  d_in[1];
    const float* Wqkv  = (const float*)d_in[2];
    const float* bqkv  = (const float*)d_in[3];
    const float* Wo    = (const float*)d_in[4];
    const float* bo    = (const float*)d_in[5];
    const float* ln1g  = (const float*)d_in[6];
    const float* ln1b  = (const float*)d_in[7];
    const float* W1    = (const float*)d_in[8];
    const float* b1    = (const float*)d_in[9];
    const float* W2    = (const float*)d_in[10];
    const float* b2    = (const float*)d_in[11];
    const float* ln2g  = (const float*)d_in[12];
    const float* ln2b  = (const float*)d_in[13];
    const float* convw = (const float*)d_in[14];
    const float* convb = (const float*)d_in[15];
    const float* normg = (const float*)d_in[16];
    const float* normb = (const float*)d_in[17];
    float* out = (float*)d_out;

    float *xa, *x1, *x2, *wcf;
    __half *h, *qkv, *ao, *mlp;
    int *cellmap, *pmin;
    cudaGetSymbolAddress((void**)&h,   g_h);
    cudaGetSymbolAddress((void**)&qkv, g_qkv);
    cudaGetSymbolAddress((void**)&ao,  g_ao);
    cudaGetSymbolAddress((void**)&xa,  g_xa);
    cudaGetSymbolAddress((void**)&x1,  g_x1);
    cudaGetSymbolAddress((void**)&x2,  g_x2);
    cudaGetSymbolAddress((void**)&mlp, g_mlp);
    cudaGetSymbolAddress((void**)&wcf, g_wc);
    cudaGetSymbolAddress((void**)&cellmap, g_cellmap);
    cudaGetSymbolAddress((void**)&pmin,    g_pmin);
    __half* wh = (__half*)wcf;

    cudaFuncSetAttribute(k_attn, cudaFuncAttributeMaxDynamicSharedMemorySize,
                         ATTN_SMEM);
    cudaFuncSetAttribute(k_gemm<1>, cudaFuncAttributeMaxDynamicSharedMemorySize,
                         GEMM_SMEM);
    cudaFuncSetAttribute(k_gemm<3>, cudaFuncAttributeMaxDynamicSharedMemorySize,
                         GEMM_SMEM);

    // pre-convert all weights to fp16 in one launch
    __half* wqkv_h = wh;
    __half* wo_h   = wh + WQKV_SZ;
    __half* w1_h   = wh + WQKV_SZ + WO_SZ;
    __half* w2_h   = wh + WQKV_SZ + WO_SZ + W1_SZ;
    k_cvt4<<<(WTOT_SZ / 4 + 255) / 256, 256>>>(Wqkv, Wo, W1, W2, wh);

    // layer 0: x -> x1
    run_block(x, x1, 0, wqkv_h, bqkv, wo_h, bo, ln1g, ln1b, w1_h, b1, w2_h, b2,
              ln2g, ln2b, h, qkv, ao, xa, mlp);

    // PEGH: x1 -> x2
    k_pegh_init<<<(GRID_SZ * GRID_SZ + 127) / 128, 128>>>(cellmap, pmin);
    k_pos_min<<<N_TOK / 128, 128>>>(pos, pmin);
    k_cellmap<<<N_TOK / 128, 128>>>(pos, pmin, cellmap);
    k_pegh<<<N_TOK, 128>>>(x1, pos, pmin, cellmap, convw, convb, x2);

    // layer 1: x2 -> x1
    run_block(x2, x1, 1, wqkv_h, bqkv, wo_h, bo, ln1g, ln1b, w1_h, b1, w2_h, b2,
              ln2g, ln2b, h, qkv, ao, xa, mlp);

    // final LN -> out
    k_layernorm<0><<<N_TOK, 128>>>(x1, normg, normb, out);
}